// round 5
// baseline (speedup 1.0000x reference)
#include <cuda_runtime.h>
#include <cuda.h>
#include <cuda_fp16.h>
#include <cstdint>

// ================= problem dims =================
#define P_DIM 2048
#define Q_DIM 2048
#define NBATCH 16
#define T_DIM 256
#define K_HALF (NBATCH * T_DIM)   // 4096
#define K_TOT  (2 * K_HALF)       // 8192

// ================= gemm config =================
#define TILE_M 128
#define TILE_N 128
#define CHUNK_K 64                  // halves per k-chunk = 128 bytes per row
#define NCHUNK (K_TOT / CHUNK_K)    // 128
#define NSTAGE 3
#define A_TILE_BYTES (TILE_M * 128) // 16384
#define B_TILE_BYTES (TILE_N * 128) // 16384
#define STAGE_BYTES (A_TILE_BYTES + B_TILE_BYTES)   // 32768
#define SMEM_DATA0 1024
#define SMEM_DYN_BYTES (SMEM_DATA0 + NSTAGE * STAGE_BYTES)  // 99328

// trace constants: exp(-0.001/0.02), exp(-0.001/0.101)
#define DECAY_PM 0.95122942450071400f
#define DECAY_X  0.99014786313283800f
#define A_TRIPLET 0.0065f

#define NTRACE_BLK 256   // traces grid size == number of spike-count partials

// ============ static device scratch (no allocs allowed) ============
__device__ __half g_A[(size_t)P_DIM * K_TOT];   // [P, 8192]: [x_pre | pre]
__device__ __half g_B[(size_t)Q_DIM * K_TOT];   // [Q, 8192]: [post*(Ap+c*xt) | -Am*x_post]
__device__ unsigned int g_count_part[NTRACE_BLK];  // per-block spike counts (overwritten -> idempotent)

// ============ helpers ============
__device__ __forceinline__ uint32_t smem_u32(const void* p) {
    uint32_t a;
    asm("{ .reg .u64 t; cvta.to.shared.u64 t, %1; cvt.u32.u64 %0, t; }" : "=r"(a) : "l"(p));
    return a;
}
__device__ __forceinline__ uint32_t pack_h2(float lo, float hi) {
    __half2 h = __floats2half2_rn(lo, hi);
    return *reinterpret_cast<uint32_t*>(&h);
}

// ================= kernel 1: traces + operand packing =================
// 256 blocks x 256 threads; each thread owns one (b, n) sequence (recurrence serial in t).
__global__ void __launch_bounds__(256) traces_kernel(
    const float* __restrict__ pre,
    const float* __restrict__ post,
    const float* __restrict__ apP,
    const float* __restrict__ amP)
{
    __shared__ unsigned s_cnt[8];
    int idx = blockIdx.x * blockDim.x + threadIdx.x;   // 0..65535
    bool is_pre = idx < (NBATCH * P_DIM);
    int li = is_pre ? idx : idx - NBATCH * P_DIM;
    int n = li & (P_DIM - 1);
    int b = li >> 11;
    const float4* in4 = (const float4*)((is_pre ? pre : post) + ((size_t)(b * P_DIM + n) << 8));
    __half* o1 = (is_pre ? g_A : g_B) + (size_t)n * K_TOT + b * T_DIM;
    __half* o2 = o1 + K_HALF;
    unsigned cnt = 0;

    if (is_pre) {
        float x = 0.f;
        #pragma unroll 4
        for (int t8 = 0; t8 < T_DIM / 8; t8++) {
            float4 f0 = in4[2 * t8], f1 = in4[2 * t8 + 1];
            float fv[8] = {f0.x, f0.y, f0.z, f0.w, f1.x, f1.y, f1.z, f1.w};
            float xa[8];
            #pragma unroll
            for (int i = 0; i < 8; i++) {
                float s = fv[i];
                xa[i] = x;
                cnt += (s > 0.5f) ? 1u : 0u;
                x = DECAY_PM * (x + s);
            }
            uint4 ua, ub;
            ua.x = pack_h2(xa[0], xa[1]); ua.y = pack_h2(xa[2], xa[3]);
            ua.z = pack_h2(xa[4], xa[5]); ua.w = pack_h2(xa[6], xa[7]);
            ub.x = pack_h2(fv[0], fv[1]); ub.y = pack_h2(fv[2], fv[3]);
            ub.z = pack_h2(fv[4], fv[5]); ub.w = pack_h2(fv[6], fv[7]);
            *(uint4*)(o1 + t8 * 8) = ua;      // x_pre trace
            *(uint4*)(o2 + t8 * 8) = ub;      // raw pre spikes (exact in fp16)
        }
    } else {
        float Ap = *apP;
        float Am = *amP;
        float xm = 0.f, xt = 0.f;
        #pragma unroll 4
        for (int t8 = 0; t8 < T_DIM / 8; t8++) {
            float4 f0 = in4[2 * t8], f1 = in4[2 * t8 + 1];
            float fv[8] = {f0.x, f0.y, f0.z, f0.w, f1.x, f1.y, f1.z, f1.w};
            float v1[8], v2[8];
            #pragma unroll
            for (int i = 0; i < 8; i++) {
                float s = fv[i];
                v1[i] = s * (Ap + A_TRIPLET * xt);   // ltp + triplet coefficient
                v2[i] = -Am * xm;                    // -ltd coefficient
                cnt += (s > 0.5f) ? 1u : 0u;
                xm = DECAY_PM * (xm + s);
                xt = DECAY_X * (xt + s);
            }
            uint4 ua, ub;
            ua.x = pack_h2(v1[0], v1[1]); ua.y = pack_h2(v1[2], v1[3]);
            ua.z = pack_h2(v1[4], v1[5]); ua.w = pack_h2(v1[6], v1[7]);
            ub.x = pack_h2(v2[0], v2[1]); ub.y = pack_h2(v2[2], v2[3]);
            ub.z = pack_h2(v2[4], v2[5]); ub.w = pack_h2(v2[6], v2[7]);
            *(uint4*)(o1 + t8 * 8) = ua;
            *(uint4*)(o2 + t8 * 8) = ub;
        }
    }
    // deterministic spike-count: warp reduce -> block reduce -> overwrite partial slot
    #pragma unroll
    for (int o = 16; o; o >>= 1) cnt += __shfl_xor_sync(0xffffffffu, cnt, o);
    if ((threadIdx.x & 31) == 0) s_cnt[threadIdx.x >> 5] = cnt;
    __syncthreads();
    if (threadIdx.x == 0) {
        unsigned t = 0;
        #pragma unroll
        for (int i = 0; i < 8; i++) t += s_cnt[i];
        g_count_part[blockIdx.x] = t;   // overwrite: idempotent across graph replays
    }
}

// ================= mma.sync building blocks (sm_80-compatible PTX) =============
__device__ __forceinline__ void ldsm4(uint32_t& r0, uint32_t& r1, uint32_t& r2, uint32_t& r3,
                                      uint32_t addr) {
    asm volatile("ldmatrix.sync.aligned.m8n8.x4.shared.b16 {%0,%1,%2,%3}, [%4];"
                 : "=r"(r0), "=r"(r1), "=r"(r2), "=r"(r3) : "r"(addr));
}
__device__ __forceinline__ void mma16816(float* d, const uint32_t* a, uint32_t b0, uint32_t b1) {
    asm volatile(
        "mma.sync.aligned.m16n8k16.row.col.f32.f16.f16.f32 "
        "{%0,%1,%2,%3}, {%4,%5,%6,%7}, {%8,%9}, {%0,%1,%2,%3};"
        : "+f"(d[0]), "+f"(d[1]), "+f"(d[2]), "+f"(d[3])
        : "r"(a[0]), "r"(a[1]), "r"(a[2]), "r"(a[3]), "r"(b0), "r"(b1));
}
__device__ __forceinline__ void cpasync16(uint32_t dst, const void* src) {
    asm volatile("cp.async.cg.shared.global [%0], [%1], 16;" :: "r"(dst), "l"(src));
}

// ================= kernel 2: GEMM + fused epilogue =================
// grid (16,16) = 256 CTAs, 128 threads. D[p,q] = A[p,:].B[q,:]^T over K=8192.
// out = clip(weights + D * scale, -2, 2)
__global__ void __launch_bounds__(128) stdp_gemm_kernel(
    const float* __restrict__ weights,
    float* __restrict__ out)
{
    extern __shared__ __align__(1024) char smem[];
    uint32_t sb = smem_u32(smem);
    int tid = threadIdx.x;
    int wid = tid >> 5, lane = tid & 31;
    int m0 = blockIdx.x * TILE_M;
    int q0 = blockIdx.y * TILE_N;

    int wm = (wid & 1) * 64;        // warp M offset (warp grid 2x2, warp tile 64x64)
    int wn = (wid >> 1) * 64;       // warp N offset
    const __half* Ag = g_A;
    const __half* Bg = g_B;

    float acc[128];
    #pragma unroll
    for (int i = 0; i < 128; i++) acc[i] = 0.f;

    // stage loader: 128 threads x 16B, 8 iters per operand
    auto load_stage = [&](int s, int kbase) {
        uint32_t a_s = sb + SMEM_DATA0 + s * STAGE_BYTES;
        uint32_t b_s = a_s + A_TILE_BYTES;
        #pragma unroll
        for (int i = 0; i < 8; i++) {
            int id = i * 128 + tid;            // 0..1023
            int row = id >> 3, ch = id & 7;
            uint32_t so = (uint32_t)(row * 128 + ((ch ^ (row & 7)) << 4));
            cpasync16(a_s + so, Ag + (size_t)(m0 + row) * K_TOT + kbase + ch * 8);
            cpasync16(b_s + so, Bg + (size_t)(q0 + row) * K_TOT + kbase + ch * 8);
        }
    };

    load_stage(0, 0);
    asm volatile("cp.async.commit_group;" ::: "memory");
    load_stage(1, CHUNK_K);
    asm volatile("cp.async.commit_group;" ::: "memory");

    int s_cur = 0, s_nxt = 2;
    #pragma unroll 1
    for (int c = 0; c < NCHUNK; c++) {
        asm volatile("cp.async.wait_group 1;" ::: "memory");
        __syncthreads();
        if (c + 2 < NCHUNK) load_stage(s_nxt, (c + 2) * CHUNK_K);
        asm volatile("cp.async.commit_group;" ::: "memory");

        uint32_t a_s = sb + SMEM_DATA0 + s_cur * STAGE_BYTES;
        uint32_t b_s = a_s + A_TILE_BYTES;
        #pragma unroll
        for (int kk = 0; kk < 4; kk++) {
            uint32_t af[4][4], bf[4][4];
            #pragma unroll
            for (int mt = 0; mt < 4; mt++) {
                int m_r = wm + mt * 16 + (lane & 15);
                int kch = kk * 2 + (lane >> 4);
                ldsm4(af[mt][0], af[mt][1], af[mt][2], af[mt][3],
                      a_s + (uint32_t)(m_r * 128 + ((kch ^ (m_r & 7)) << 4)));
            }
            #pragma unroll
            for (int pr = 0; pr < 4; pr++) {
                int g = lane >> 3;
                int n_r = wn + pr * 16 + (lane & 7) + (g >> 1) * 8;
                int kch = kk * 2 + (g & 1);
                ldsm4(bf[pr][0], bf[pr][1], bf[pr][2], bf[pr][3],
                      b_s + (uint32_t)(n_r * 128 + ((kch ^ (n_r & 7)) << 4)));
            }
            #pragma unroll
            for (int mt = 0; mt < 4; mt++) {
                #pragma unroll
                for (int nt = 0; nt < 8; nt++) {
                    int pr = nt >> 1, off = (nt & 1) * 2;
                    mma16816(&acc[(mt * 8 + nt) * 4], af[mt], bf[pr][off], bf[pr][off + 1]);
                }
            }
        }
        s_cur = (s_cur + 1 == NSTAGE) ? 0 : s_cur + 1;
        s_nxt = (s_nxt + 1 == NSTAGE) ? 0 : s_nxt + 1;
    }

    // ---- spike-count reduction (partials written by traces_kernel) ----
    // header region of dynamic smem [128,144) is never a cp.async target
    unsigned c2 = g_count_part[tid] + g_count_part[tid + 128];
    #pragma unroll
    for (int o = 16; o; o >>= 1) c2 += __shfl_xor_sync(0xffffffffu, c2, o);
    unsigned* sc = (unsigned*)(smem + 128);
    if (lane == 0) sc[wid] = c2;
    __syncthreads();
    float act = (float)(sc[0] + sc[1] + sc[2] + sc[3]) * (1.0f / (NBATCH * T_DIM));
    float scale = sqrtf(0.1f / (act + 1e-6f));

    // ---- fused epilogue ----
    #pragma unroll
    for (int mt = 0; mt < 4; mt++) {
        int r0 = m0 + wm + mt * 16 + (lane >> 2);
        #pragma unroll
        for (int nt = 0; nt < 8; nt++) {
            int cidx = q0 + wn + nt * 8 + (lane & 3) * 2;
            const float* d = &acc[(mt * 8 + nt) * 4];
            {
                const float2 w = *(const float2*)(weights + (size_t)r0 * Q_DIM + cidx);
                float2 o;
                o.x = fminf(fmaxf(fmaf(d[0], scale, w.x), -2.f), 2.f);
                o.y = fminf(fmaxf(fmaf(d[1], scale, w.y), -2.f), 2.f);
                *(float2*)(out + (size_t)r0 * Q_DIM + cidx) = o;
            }
            {
                const float2 w = *(const float2*)(weights + (size_t)(r0 + 8) * Q_DIM + cidx);
                float2 o;
                o.x = fminf(fmaxf(fmaf(d[2], scale, w.x), -2.f), 2.f);
                o.y = fminf(fmaxf(fmaf(d[3], scale, w.y), -2.f), 2.f);
                *(float2*)(out + (size_t)(r0 + 8) * Q_DIM + cidx) = o;
            }
        }
    }
}

// ================= host =================
extern "C" void kernel_launch(void* const* d_in, const int* in_sizes, int n_in,
                              void* d_out, int out_size)
{
    const float* pre  = (const float*)d_in[0];
    const float* post = (const float*)d_in[1];
    const float* w    = (const float*)d_in[2];
    const float* ap   = (const float*)d_in[3];
    const float* am   = (const float*)d_in[4];
    float* out = (float*)d_out;

    traces_kernel<<<NTRACE_BLK, 256>>>(pre, post, ap, am);

    cudaFuncSetAttribute(stdp_gemm_kernel, cudaFuncAttributeMaxDynamicSharedMemorySize,
                         SMEM_DYN_BYTES);
    dim3 grid(P_DIM / TILE_M, Q_DIM / TILE_N);   // (16, 16)
    stdp_gemm_kernel<<<grid, 128, SMEM_DYN_BYTES>>>(w, out);
}